// round 9
// baseline (speedup 1.0000x reference)
#include <cuda_runtime.h>
#include <cstdint>

#define NN 65536

// ---------------- globals ----------------
__device__ float g_Bf[16 * 7168];             // fragment-major folded B per v-tile

__device__ __forceinline__ uint32_t f2tf32(float f) {
    uint32_t u;
    asm("cvt.rna.tf32.f32 %0, %1;" : "=r"(u) : "f"(f));
    return u;
}

// ---------------- prep: fold weights AND scatter into fragment-major g_Bf ----------------
__global__ void __launch_bounds__(128) prep_kernel(
        const float* __restrict__ Wup0, const float* __restrict__ Wup1,
        const float* __restrict__ tpw,  const float* __restrict__ Wl0,
        const float* __restrict__ Wl1,  const float* __restrict__ Wl2) {
    const float INV_UP = 0.0883883476483184f;
    const float A2 = 0.7071067811865476f;
    const float A3 = 0.5773502691896258f;
    const float N0 = 0.0625f;
    const float N1 = 0.0510310363079829f;
    const float R3 = 0.5773502691896258f;
    const float R5 = 0.4472135954999579f;

    int sec = blockIdx.x >> 5;
    int ut  = blockIdx.x & 31;
    int v   = threadIdx.x;

    float coefBase; const float* Wl; int rowOff; int tpwIdx;
    switch (sec) {
        case 0: coefBase = A2 * N0;      Wl = Wl0; rowOff = 0;   tpwIdx = 0; break;
        case 1: coefBase = A3 * N1 * R3; Wl = Wl1; rowOff = 0;   tpwIdx = 1; break;
        case 2: coefBase = A2 * N0 * R5; Wl = Wl2; rowOff = 0;   tpwIdx = 2; break;
        case 3: coefBase = A2 * N0 * R3; Wl = Wl0; rowOff = 128; tpwIdx = 4; break;
        case 4: coefBase = A3 * N1 * R3; Wl = Wl1; rowOff = 128; tpwIdx = 3; break;
        case 5: coefBase = A3 * N1;      Wl = Wl1; rowOff = 256; tpwIdx = 6; break;
        default:coefBase = A2 * N0;      Wl = Wl2; rowOff = 128; tpwIdx = 5; break;
    }
    coefBase *= INV_UP;
    const float* Wup = (sec < 3) ? Wup0 : Wup1;

    __shared__ float sWup[4 * 128];
    __shared__ float scoef[128];
#pragma unroll
    for (int i = 0; i < 4; i++)
        sWup[i * 128 + v] = Wup[(size_t)(ut * 4 + i) * 128 + v];
    scoef[v] = coefBase * tpw[tpwIdx * 128 + v];
    __syncthreads();

    float acc[4];
#pragma unroll
    for (int i = 0; i < 4; i++) acc[i] = 0.f;

#pragma unroll 8
    for (int k = 0; k < 128; k++) {
        float tv = scoef[k] * Wl[(size_t)(rowOff + k) * 128 + v];
#pragma unroll
        for (int uu = 0; uu < 4; uu++) acc[uu] += sWup[uu * 128 + k] * tv;
    }

    int vt = v >> 3, gidv = v & 7;
#pragma unroll
    for (int uu = 0; uu < 4; uu++) {
        int u = ut * 4 + uu;
        int ks = u >> 3, rem = u & 7;
        int tig = rem & 3, h = rem >> 2;
        int lane = gidv * 4 + tig;
        int i2 = 2 * sec + h;
        int off;
        if (i2 < 12) off = (i2 >> 2) * 2048 + (ks * 32 + lane) * 4 + (i2 & 3);
        else         off = 6144 + (ks * 32 + lane) * 2 + (i2 - 12);
        g_Bf[vt * 7168 + off] = __uint_as_float(f2tf32(acc[uu]));
    }
}

// ---------------- fused gemm + combine (round-8 structure + K-split ILP) ----------------
#define ALD 520

#define OFF_A   0                     // 64*520  = 33280
#define OFF_B   33280                 // 2*7168  = 14336
#define OFF_O   47616                 // 2*4608  =  9216
#define OFF_MF  56832                 //            576
#define SMEM_FLOATS 57408             // 229632 bytes (proven fit)

__device__ __forceinline__ void cp16(uint32_t dst, const void* src) {
    asm volatile("cp.async.cg.shared.global [%0], [%1], 16;" :: "r"(dst), "l"(src));
}
__device__ __forceinline__ void cp_commit() {
    asm volatile("cp.async.commit_group;");
}
__device__ __forceinline__ void group_bar(int id) {
    asm volatile("bar.sync %0, 128;" :: "r"(id) : "memory");
}

__device__ __forceinline__ void mma_tf32(float* d, const uint32_t* a, const uint32_t* b) {
    asm volatile(
        "mma.sync.aligned.m16n8k8.row.col.f32.tf32.tf32.f32 "
        "{%0,%1,%2,%3}, {%4,%5,%6,%7}, {%8,%9}, {%0,%1,%2,%3};"
        : "+f"(d[0]), "+f"(d[1]), "+f"(d[2]), "+f"(d[3])
        : "r"(a[0]), "r"(a[1]), "r"(a[2]), "r"(a[3]), "r"(b[0]), "r"(b[1]));
}

__global__ void __launch_bounds__(256, 1) fused_kernel(
        const float* __restrict__ nf, const float* __restrict__ mf,
        float* __restrict__ out) {
    extern __shared__ float sm[];
    uint32_t sbase = (uint32_t)__cvta_generic_to_shared(sm);

    int t = threadIdx.x;
    int wid = t >> 5, lane = t & 31;
    int grp = wid >> 2;
    int wg  = wid & 3;
    int gt  = t & 127;
    int gid = lane >> 2, tig = lane & 3;
    size_t nodeBase = (size_t)blockIdx.x * 64;

    {
        const float* srcA = nf + nodeBase * 512;
#pragma unroll
        for (int i = 0; i < 32; i++) {
            int idx = i * 256 + t;
            int node = idx >> 7, f4 = idx & 127;
            cp16(sbase + (OFF_A + node * ALD + f4 * 4) * 4,
                 srcA + (size_t)node * 512 + f4 * 4);
        }
        if (t < 144) cp16(sbase + (OFF_MF + t * 4) * 4, mf + nodeBase * 9 + t * 4);
        const float* srcB = g_Bf + (size_t)grp * 7168;
#pragma unroll
        for (int i = 0; i < 14; i++) {
            int idx = i * 128 + gt;
            cp16(sbase + (OFF_B + grp * 7168 + idx * 4) * 4, srcB + idx * 4);
        }
        cp_commit();
    }
    asm volatile("cp.async.wait_group 0;");
    __syncthreads();

    // one-time in-place permute + tf32 convert of A
    for (int id = t; id < 1024; id += 256) {
        int row = id >> 4, ks = id & 15;
        float* rp = sm + row * ALD;
        float4 q0 = *reinterpret_cast<float4*>(rp + ks * 8);
        float4 q1 = *reinterpret_cast<float4*>(rp + ks * 8 + 4);
        uint4 o0 = make_uint4(f2tf32(q0.x), f2tf32(q1.x), f2tf32(q0.y), f2tf32(q1.y));
        uint4 o1 = make_uint4(f2tf32(q0.z), f2tf32(q1.z), f2tf32(q0.w), f2tf32(q1.w));
        *reinterpret_cast<uint4*>(rp + ks * 8)     = o0;
        *reinterpret_cast<uint4*>(rp + ks * 8 + 4) = o1;
        float r[24];
        float* vp = rp + 128 + 24 * ks;
#pragma unroll
        for (int q = 0; q < 6; q++)
            *reinterpret_cast<float4*>(r + q * 4) = *reinterpret_cast<float4*>(vp + q * 4);
        const int perm[8] = {0, 4, 1, 5, 2, 6, 3, 7};
        uint32_t w[24];
#pragma unroll
        for (int a = 0; a < 3; a++)
#pragma unroll
            for (int i = 0; i < 8; i++)
                w[a * 8 + i] = f2tf32(r[3 * perm[i] + a]);
#pragma unroll
        for (int q = 0; q < 6; q++)
            *reinterpret_cast<uint4*>(vp + q * 4) = *reinterpret_cast<uint4*>(w + q * 4);
    }
    __syncthreads();

    const float r2 = 0.7071067811865476f;
    const float r6 = 0.4082482904638631f;
    const float i5 = 0.4472135954999579f;

    int rb = wg * 16;
    int r0row = (rb + gid) * ALD;
    int r1row = (rb + gid + 8) * ALD;
    const float* sB = sm + OFF_B + grp * 7168;
    float* sO = sm + OFF_O + grp * 4608;
    int barId = grp + 1;

    for (int i = 0; i < 8; i++) {
        int p = 2 * i + grp;

        asm volatile("cp.async.wait_group 0;");
        group_bar(barId);

        // two independent accumulator sets over ks parity -> 30 indep chains
        float acc[2][15][4];
#pragma unroll
        for (int e = 0; e < 2; e++)
#pragma unroll
            for (int n = 0; n < 15; n++)
#pragma unroll
                for (int q = 0; q < 4; q++) acc[e][n][q] = 0.f;

#pragma unroll 4
        for (int kp = 0; kp < 8; kp++) {
#pragma unroll
            for (int e = 0; e < 2; e++) {
                int ks = kp * 2 + e;
                uint32_t ar[4][4];
                {
                    float2 s0 = *reinterpret_cast<const float2*>(sm + r0row + ks * 8 + 2 * tig);
                    float2 s1 = *reinterpret_cast<const float2*>(sm + r1row + ks * 8 + 2 * tig);
                    ar[0][0] = __float_as_uint(s0.x); ar[0][2] = __float_as_uint(s0.y);
                    ar[0][1] = __float_as_uint(s1.x); ar[0][3] = __float_as_uint(s1.y);
                }
#pragma unroll
                for (int a = 0; a < 3; a++) {
                    int c0 = 128 + 24 * ks + 8 * a + 2 * tig;
                    float2 v0 = *reinterpret_cast<const float2*>(sm + r0row + c0);
                    float2 v1 = *reinterpret_cast<const float2*>(sm + r1row + c0);
                    ar[a + 1][0] = __float_as_uint(v0.x); ar[a + 1][2] = __float_as_uint(v0.y);
                    ar[a + 1][1] = __float_as_uint(v1.x); ar[a + 1][3] = __float_as_uint(v1.y);
                }
                int slot = ks * 32 + lane;
                float4 b01 = *reinterpret_cast<const float4*>(sB + slot * 4);
                float4 b23 = *reinterpret_cast<const float4*>(sB + 2048 + slot * 4);
                float4 b45 = *reinterpret_cast<const float4*>(sB + 4096 + slot * 4);
                float2 b6  = *reinterpret_cast<const float2*>(sB + 6144 + slot * 2);
                uint32_t bf[7][2] = {
                    {__float_as_uint(b01.x), __float_as_uint(b01.y)},
                    {__float_as_uint(b01.z), __float_as_uint(b01.w)},
                    {__float_as_uint(b23.x), __float_as_uint(b23.y)},
                    {__float_as_uint(b23.z), __float_as_uint(b23.w)},
                    {__float_as_uint(b45.x), __float_as_uint(b45.y)},
                    {__float_as_uint(b45.z), __float_as_uint(b45.w)},
                    {__float_as_uint(b6.x),  __float_as_uint(b6.y)}};
#pragma unroll
                for (int j = 0; j < 3; j++) mma_tf32(acc[e][j], ar[0], bf[j]);
#pragma unroll
                for (int a = 0; a < 3; a++)
#pragma unroll
                    for (int j = 0; j < 4; j++)
                        mma_tf32(acc[e][3 + a * 4 + j], ar[a + 1], bf[3 + j]);
            }
        }
        // merge parity accumulators
#pragma unroll
        for (int n = 0; n < 15; n++)
#pragma unroll
            for (int q = 0; q < 4; q++) acc[0][n][q] += acc[1][n][q];

        group_bar(barId);
        if (i < 7) {
            const float* srcB = g_Bf + (size_t)(p + 2) * 7168;
#pragma unroll
            for (int q = 0; q < 14; q++) {
                int idx = q * 128 + gt;
                cp16(sbase + (OFF_B + grp * 7168 + idx * 4) * 4, srcB + idx * 4);
            }
            cp_commit();
        }

        // combine -> smem staging
#pragma unroll
        for (int r = 0; r < 2; r++) {
            int nl = rb + gid + r * 8;
            const float* f = sm + OFF_MF + nl * 9;
            float f0  = f[0];
            float f1a = f[1], f1b = f[2], f1c = f[3];
            float f2a = f[4], f2b = f[5], f2c = f[6], f2d = f[7], f2e = f[8];

            float A00 = -f2c * r6 - f2e * r2;
            float A11 = 2.f * f2c * r6;
            float A22 = -f2c * r6 + f2e * r2;
            float A01 = f2b * r2, A02 = f2a * r2, A12 = f2d * r2;

#pragma unroll
            for (int c = 0; c < 2; c++) {
                int ai = r * 2 + c;
                int vl = tig * 2 + c;
                float y0 = acc[0][0][ai], y1 = acc[0][1][ai], y2 = acc[0][2][ai];
                float z00 = acc[0][3][ai],  z01 = acc[0][4][ai];
                float z02 = acc[0][5][ai],  z03 = acc[0][6][ai];
                float z10 = acc[0][7][ai],  z11 = acc[0][8][ai];
                float z12 = acc[0][9][ai],  z13 = acc[0][10][ai];
                float z20 = acc[0][11][ai], z21 = acc[0][12][ai];
                float z22 = acc[0][13][ai], z23 = acc[0][14][ai];

                float* o = sO + nl * 72 + vl * 9;
                o[0] = f0 * y0 + f1a * z00 + f1b * z10 + f1c * z20;
                o[1] = f1a * y1 + f0 * z01 + i5 * (A00 * z02 + A01 * z12 + A02 * z22);
                o[2] = f1b * y1 + f0 * z11 + i5 * (A01 * z02 + A11 * z12 + A12 * z22);
                o[3] = f1c * y1 + f0 * z21 + i5 * (A02 * z02 + A12 * z12 + A22 * z22);
                o[4] = f2a * y2 + i5 * (f1c * r2 * z03 + f1a * r2 * z23);
                o[5] = f2b * y2 + i5 * (f1b * r2 * z03 + f1a * r2 * z13);
                o[6] = f2c * y2 + i5 * ((-f1a * z03 + 2.f * f1b * z13 - f1c * z23) * r6);
                o[7] = f2d * y2 + i5 * (f1c * r2 * z13 + f1b * r2 * z23);
                o[8] = f2e * y2 + i5 * ((-f1a * z03 + f1c * z23) * r2);
            }
        }
        group_bar(barId);

#pragma unroll
        for (int q = 0; q < 9; q++) {
            int idx = q * 128 + gt;
            int node = idx / 18, f4i = idx - node * 18;
            float4 v4 = *reinterpret_cast<const float4*>(sO + node * 72 + f4i * 4);
            *reinterpret_cast<float4*>(out + (nodeBase + node) * 1152 + p * 72 + f4i * 4) = v4;
        }
        group_bar(barId);
    }
}

// ---------------- launch ----------------
extern "C" void kernel_launch(void* const* d_in, const int* in_sizes, int n_in,
                              void* d_out, int out_size) {
    const float* nf   = (const float*)d_in[0];
    const float* mf   = (const float*)d_in[1];
    const float* Wup0 = (const float*)d_in[2];
    const float* Wup1 = (const float*)d_in[3];
    const float* tpw  = (const float*)d_in[4];
    const float* Wl0  = (const float*)d_in[5];
    const float* Wl1  = (const float*)d_in[6];
    const float* Wl2  = (const float*)d_in[7];
    float* out = (float*)d_out;

    static bool attrSet = false;
    if (!attrSet) {
        cudaFuncSetAttribute(fused_kernel, cudaFuncAttributeMaxDynamicSharedMemorySize,
                             SMEM_FLOATS * 4);
        attrSet = true;
    }

    prep_kernel<<<224, 128>>>(Wup0, Wup1, tpw, Wl0, Wl1, Wl2);
    fused_kernel<<<NN / 64, 256, SMEM_FLOATS * 4>>>(nf, mf, out);
}

// round 11
// speedup vs baseline: 1.6734x; 1.6734x over previous
#include <cuda_runtime.h>
#include <cstdint>

#define NN 65536

// ---------------- globals ----------------
__device__ float g_Bf[16 * 7168];             // fragment-major folded B per v-tile

__device__ __forceinline__ uint32_t f2tf32(float f) {
    uint32_t u;
    asm("cvt.rna.tf32.f32 %0, %1;" : "=r"(u) : "f"(f));
    return u;
}

// ---------------- prep: fold weights, scatter into fragment-major g_Bf ----------------
// grid: 7 sections x 128 u-rows = 896 blocks, 128 threads (v). One u-row per block.
__global__ void __launch_bounds__(128) prep_kernel(
        const float* __restrict__ Wup0, const float* __restrict__ Wup1,
        const float* __restrict__ tpw,  const float* __restrict__ Wl0,
        const float* __restrict__ Wl1,  const float* __restrict__ Wl2) {
    const float INV_UP = 0.0883883476483184f;   // 1/sqrt(128)
    const float A2 = 0.7071067811865476f;       // 1/sqrt(2)
    const float A3 = 0.5773502691896258f;       // 1/sqrt(3)
    const float N0 = 0.0625f;                   // 1/sqrt(256)
    const float N1 = 0.0510310363079829f;       // 1/sqrt(384)
    const float R3 = 0.5773502691896258f;       // CG 1/sqrt(3)
    const float R5 = 0.4472135954999579f;       // CG 1/sqrt(5)

    int sec = blockIdx.x >> 7;     // 0..6
    int u   = blockIdx.x & 127;    // up-channel (GEMM K index)
    int v   = threadIdx.x;         // 0..127

    float coefBase; const float* Wl; int rowOff; int tpwIdx;
    switch (sec) {
        case 0: coefBase = A2 * N0;      Wl = Wl0; rowOff = 0;   tpwIdx = 0; break;
        case 1: coefBase = A3 * N1 * R3; Wl = Wl1; rowOff = 0;   tpwIdx = 1; break;
        case 2: coefBase = A2 * N0 * R5; Wl = Wl2; rowOff = 0;   tpwIdx = 2; break;
        case 3: coefBase = A2 * N0 * R3; Wl = Wl0; rowOff = 128; tpwIdx = 4; break;
        case 4: coefBase = A3 * N1 * R3; Wl = Wl1; rowOff = 128; tpwIdx = 3; break;
        case 5: coefBase = A3 * N1;      Wl = Wl1; rowOff = 256; tpwIdx = 6; break;
        default:coefBase = A2 * N0;      Wl = Wl2; rowOff = 128; tpwIdx = 5; break;
    }
    coefBase *= INV_UP;
    const float* Wup = ((sec < 3) ? Wup0 : Wup1) + (size_t)u * 128;
    const float* tw  = tpw + tpwIdx * 128;
    const float* WlR = Wl + (size_t)rowOff * 128 + v;

    float acc = 0.f;
#pragma unroll 16
    for (int k = 0; k < 128; k++) {
        // Wup[k], tw[k] warp-uniform; WlR coalesced over v. Wl fits in L2.
        acc += (coefBase * tw[k] * Wup[k]) * WlR[(size_t)k * 128];
    }

    // scatter into fragment-major layout (same mapping as rounds 8/9, verified)
    int ks = u >> 3, rem = u & 7;
    int tig = rem & 3, h = rem >> 2;
    int vt = v >> 3, gidv = v & 7;
    int lane = gidv * 4 + tig;
    int i2 = 2 * sec + h;
    int off;
    if (i2 < 12) off = (i2 >> 2) * 2048 + (ks * 32 + lane) * 4 + (i2 & 3);
    else         off = 6144 + (ks * 32 + lane) * 2 + (i2 - 12);
    g_Bf[vt * 7168 + off] = __uint_as_float(f2tf32(acc));
}

// ---------------- fused gemm + combine (round-6 structure, correct offsets) ----------------
// 64 nodes/block, 256 threads = 8 warps = 2 groups x 4 m-tiles of 16 rows.
#define ALD 516

// smem float offsets  (two-group layout — OFF_MF must follow BOTH O buffers)
#define OFF_A   0                     // 64*516  = 33024
#define OFF_B   33024                 // 2*7168  = 14336
#define OFF_O   47360                 // 2*4608  =  9216  (ends at 56576)
#define OFF_MF  56576                 //            576
#define SMEM_FLOATS 57152             // *4 = 228608 bytes

__device__ __forceinline__ void cp16(uint32_t dst, const void* src) {
    asm volatile("cp.async.cg.shared.global [%0], [%1], 16;" :: "r"(dst), "l"(src));
}
__device__ __forceinline__ void cp_commit() {
    asm volatile("cp.async.commit_group;");
}
__device__ __forceinline__ void group_bar(int id) {
    asm volatile("bar.sync %0, 128;" :: "r"(id) : "memory");
}

__device__ __forceinline__ void mma_tf32(float* d, const uint32_t* a, const uint32_t* b) {
    asm volatile(
        "mma.sync.aligned.m16n8k8.row.col.f32.tf32.tf32.f32 "
        "{%0,%1,%2,%3}, {%4,%5,%6,%7}, {%8,%9}, {%0,%1,%2,%3};"
        : "+f"(d[0]), "+f"(d[1]), "+f"(d[2]), "+f"(d[3])
        : "r"(a[0]), "r"(a[1]), "r"(a[2]), "r"(a[3]), "r"(b[0]), "r"(b[1]));
}

__global__ void __launch_bounds__(256, 1) fused_kernel(
        const float* __restrict__ nf, const float* __restrict__ mf,
        float* __restrict__ out) {
    extern __shared__ float sm[];
    uint32_t sbase = (uint32_t)__cvta_generic_to_shared(sm);

    int t = threadIdx.x;                 // 0..255
    int wid = t >> 5, lane = t & 31;
    int grp = wid >> 2;                  // 0/1
    int wg  = wid & 3;                   // m-tile within group
    int gt  = t & 127;                   // thread-in-group
    int gid = lane >> 2, tig = lane & 3;
    size_t nodeBase = (size_t)blockIdx.x * 64;

    // ---- initial staging: A raw + mf + group's first B tile ----
    {
        const float* srcA = nf + nodeBase * 512;
#pragma unroll
        for (int i = 0; i < 32; i++) {
            int idx = i * 256 + t;
            int node = idx >> 7, f4 = idx & 127;
            cp16(sbase + (OFF_A + node * ALD + f4 * 4) * 4,
                 srcA + (size_t)node * 512 + f4 * 4);
        }
        if (t < 144) cp16(sbase + (OFF_MF + t * 4) * 4, mf + nodeBase * 9 + t * 4);
        const float* srcB = g_Bf + (size_t)grp * 7168;   // first pass p0 = grp
#pragma unroll
        for (int i = 0; i < 14; i++) {
            int idx = i * 128 + gt;
            cp16(sbase + (OFF_B + grp * 7168 + idx * 4) * 4, srcB + idx * 4);
        }
        cp_commit();
    }
    asm volatile("cp.async.wait_group 0;");
    __syncthreads();

    // ---- in-place tf32 conversion of A (once) ----
#pragma unroll
    for (int i = 0; i < 33; i++) {
        int idx = i * 256 + t;
        if (idx < 8256) {
            float4 v4 = *reinterpret_cast<float4*>(sm + idx * 4);
            uint4 o = make_uint4(f2tf32(v4.x), f2tf32(v4.y), f2tf32(v4.z), f2tf32(v4.w));
            *reinterpret_cast<uint4*>(sm + idx * 4) = o;
        }
    }
    __syncthreads();

    const float r2 = 0.7071067811865476f;
    const float r6 = 0.4082482904638631f;
    const float i5 = 0.4472135954999579f;

    int rb = wg * 16;
    int r0row = (rb + gid) * ALD;
    int r1row = (rb + gid + 8) * ALD;
    const float* sB = sm + OFF_B + grp * 7168;
    float* sO = sm + OFF_O + grp * 4608;
    int barId = grp + 1;

    for (int i = 0; i < 8; i++) {
        int p = 2 * i + grp;

        asm volatile("cp.async.wait_group 0;");
        group_bar(barId);                      // B[p] visible to whole group

        float acc[15][4];
#pragma unroll
        for (int n = 0; n < 15; n++)
#pragma unroll
            for (int q = 0; q < 4; q++) acc[n][q] = 0.f;

#pragma unroll
        for (int ks = 0; ks < 16; ks++) {
            int kt = ks * 8 + tig;
            uint32_t ar[4][4];
            ar[0][0] = __float_as_uint(sm[r0row + kt]);
            ar[0][1] = __float_as_uint(sm[r1row + kt]);
            ar[0][2] = __float_as_uint(sm[r0row + kt + 4]);
            ar[0][3] = __float_as_uint(sm[r1row + kt + 4]);
#pragma unroll
            for (int a = 0; a < 3; a++) {
                int c0 = 128 + 3 * kt + a;
                ar[a + 1][0] = __float_as_uint(sm[r0row + c0]);
                ar[a + 1][1] = __float_as_uint(sm[r1row + c0]);
                ar[a + 1][2] = __float_as_uint(sm[r0row + c0 + 12]);
                ar[a + 1][3] = __float_as_uint(sm[r1row + c0 + 12]);
            }
            int slot = ks * 32 + lane;
            float4 b01 = *reinterpret_cast<const float4*>(sB + slot * 4);
            float4 b23 = *reinterpret_cast<const float4*>(sB + 2048 + slot * 4);
            float4 b45 = *reinterpret_cast<const float4*>(sB + 4096 + slot * 4);
            float2 b6  = *reinterpret_cast<const float2*>(sB + 6144 + slot * 2);
            uint32_t bf[7][2] = {
                {__float_as_uint(b01.x), __float_as_uint(b01.y)},
                {__float_as_uint(b01.z), __float_as_uint(b01.w)},
                {__float_as_uint(b23.x), __float_as_uint(b23.y)},
                {__float_as_uint(b23.z), __float_as_uint(b23.w)},
                {__float_as_uint(b45.x), __float_as_uint(b45.y)},
                {__float_as_uint(b45.z), __float_as_uint(b45.w)},
                {__float_as_uint(b6.x),  __float_as_uint(b6.y)}};
#pragma unroll
            for (int j = 0; j < 3; j++) mma_tf32(acc[j], ar[0], bf[j]);
#pragma unroll
            for (int a = 0; a < 3; a++)
#pragma unroll
                for (int j = 0; j < 4; j++) mma_tf32(acc[3 + a * 4 + j], ar[a + 1], bf[3 + j]);
        }

        group_bar(barId);                      // group done reading B[p]
        if (i < 7) {                           // prefetch B[p+2] (overlaps combine/store)
            const float* srcB = g_Bf + (size_t)(p + 2) * 7168;
#pragma unroll
            for (int q = 0; q < 14; q++) {
                int idx = q * 128 + gt;
                cp16(sbase + (OFF_B + grp * 7168 + idx * 4) * 4, srcB + idx * 4);
            }
            cp_commit();
        }

        // ---- combine -> smem staging ----
#pragma unroll
        for (int r = 0; r < 2; r++) {
            int nl = rb + gid + r * 8;
            const float* f = sm + OFF_MF + nl * 9;
            float f0  = f[0];
            float f1a = f[1], f1b = f[2], f1c = f[3];
            float f2a = f[4], f2b = f[5], f2c = f[6], f2d = f[7], f2e = f[8];

            float A00 = -f2c * r6 - f2e * r2;
            float A11 = 2.f * f2c * r6;
            float A22 = -f2c * r6 + f2e * r2;
            float A01 = f2b * r2, A02 = f2a * r2, A12 = f2d * r2;

#pragma unroll
            for (int c = 0; c < 2; c++) {
                int ai = r * 2 + c;
                int vl = tig * 2 + c;
                float y0 = acc[0][ai], y1 = acc[1][ai], y2 = acc[2][ai];
                float z00 = acc[3][ai],  z01 = acc[4][ai],  z02 = acc[5][ai],  z03 = acc[6][ai];
                float z10 = acc[7][ai],  z11 = acc[8][ai],  z12 = acc[9][ai],  z13 = acc[10][ai];
                float z20 = acc[11][ai], z21 = acc[12][ai], z22 = acc[13][ai], z23 = acc[14][ai];

                float* o = sO + nl * 72 + vl * 9;
                o[0] = f0 * y0 + f1a * z00 + f1b * z10 + f1c * z20;
                o[1] = f1a * y1 + f0 * z01 + i5 * (A00 * z02 + A01 * z12 + A02 * z22);
                o[2] = f1b * y1 + f0 * z11 + i5 * (A01 * z02 + A11 * z12 + A12 * z22);
                o[3] = f1c * y1 + f0 * z21 + i5 * (A02 * z02 + A12 * z12 + A22 * z22);
                o[4] = f2a * y2 + i5 * (f1c * r2 * z03 + f1a * r2 * z23);
                o[5] = f2b * y2 + i5 * (f1b * r2 * z03 + f1a * r2 * z13);
                o[6] = f2c * y2 + i5 * ((-f1a * z03 + 2.f * f1b * z13 - f1c * z23) * r6);
                o[7] = f2d * y2 + i5 * (f1c * r2 * z13 + f1b * r2 * z23);
                o[8] = f2e * y2 + i5 * ((-f1a * z03 + f1c * z23) * r2);
            }
        }
        group_bar(barId);                      // out tile staged

        // coalesced store: 64 nodes x 72 floats -> out[n*1152 + p*72 ..)
#pragma unroll
        for (int q = 0; q < 9; q++) {
            int idx = q * 128 + gt;            // 1152 float4s
            int node = idx / 18, f4i = idx - node * 18;
            float4 v4 = *reinterpret_cast<const float4*>(sO + node * 72 + f4i * 4);
            *reinterpret_cast<float4*>(out + (nodeBase + node) * 1152 + p * 72 + f4i * 4) = v4;
        }
        group_bar(barId);                      // out buffer free for next pass
    }
}

// ---------------- launch ----------------
extern "C" void kernel_launch(void* const* d_in, const int* in_sizes, int n_in,
                              void* d_out, int out_size) {
    const float* nf   = (const float*)d_in[0];
    const float* mf   = (const float*)d_in[1];
    const float* Wup0 = (const float*)d_in[2];
    const float* Wup1 = (const float*)d_in[3];
    const float* tpw  = (const float*)d_in[4];
    const float* Wl0  = (const float*)d_in[5];
    const float* Wl1  = (const float*)d_in[6];
    const float* Wl2  = (const float*)d_in[7];
    float* out = (float*)d_out;

    static bool attrSet = false;
    if (!attrSet) {
        cudaFuncSetAttribute(fused_kernel, cudaFuncAttributeMaxDynamicSharedMemorySize,
                             SMEM_FLOATS * 4);
        attrSet = true;
    }

    prep_kernel<<<896, 128>>>(Wup0, Wup1, tpw, Wl0, Wl1, Wl2);
    fused_kernel<<<NN / 64, 256, SMEM_FLOATS * 4>>>(nf, mf, out);
}

// round 12
// speedup vs baseline: 1.6751x; 1.0010x over previous
#include <cuda_runtime.h>
#include <cstdint>

#define NN 65536

// ---------------- globals ----------------
__device__ float g_Bf[16 * 7168];             // fragment-major folded B per v-tile

__device__ __forceinline__ uint32_t f2tf32(float f) {
    uint32_t u;
    asm("cvt.rna.tf32.f32 %0, %1;" : "=r"(u) : "f"(f));
    return u;
}

// ---------------- prep: fold weights, scatter into fragment-major g_Bf ----------------
// grid: 7 sections x 128 u-rows = 896 blocks, 128 threads (v). One u-row per block.
__global__ void __launch_bounds__(128) prep_kernel(
        const float* __restrict__ Wup0, const float* __restrict__ Wup1,
        const float* __restrict__ tpw,  const float* __restrict__ Wl0,
        const float* __restrict__ Wl1,  const float* __restrict__ Wl2) {
    const float INV_UP = 0.0883883476483184f;   // 1/sqrt(128)
    const float A2 = 0.7071067811865476f;       // 1/sqrt(2)
    const float A3 = 0.5773502691896258f;       // 1/sqrt(3)
    const float N0 = 0.0625f;                   // 1/sqrt(256)
    const float N1 = 0.0510310363079829f;       // 1/sqrt(384)
    const float R3 = 0.5773502691896258f;       // CG 1/sqrt(3)
    const float R5 = 0.4472135954999579f;       // CG 1/sqrt(5)

    int sec = blockIdx.x >> 7;     // 0..6
    int u   = blockIdx.x & 127;    // up-channel (GEMM K index)
    int v   = threadIdx.x;         // 0..127

    float coefBase; const float* Wl; int rowOff; int tpwIdx;
    switch (sec) {
        case 0: coefBase = A2 * N0;      Wl = Wl0; rowOff = 0;   tpwIdx = 0; break;
        case 1: coefBase = A3 * N1 * R3; Wl = Wl1; rowOff = 0;   tpwIdx = 1; break;
        case 2: coefBase = A2 * N0 * R5; Wl = Wl2; rowOff = 0;   tpwIdx = 2; break;
        case 3: coefBase = A2 * N0 * R3; Wl = Wl0; rowOff = 128; tpwIdx = 4; break;
        case 4: coefBase = A3 * N1 * R3; Wl = Wl1; rowOff = 128; tpwIdx = 3; break;
        case 5: coefBase = A3 * N1;      Wl = Wl1; rowOff = 256; tpwIdx = 6; break;
        default:coefBase = A2 * N0;      Wl = Wl2; rowOff = 128; tpwIdx = 5; break;
    }
    coefBase *= INV_UP;
    const float* Wup = ((sec < 3) ? Wup0 : Wup1) + (size_t)u * 128;
    const float* tw  = tpw + tpwIdx * 128;
    const float* WlR = Wl + (size_t)rowOff * 128 + v;

    float acc = 0.f;
#pragma unroll 16
    for (int k = 0; k < 128; k++) {
        // Wup[k], tw[k] warp-uniform; WlR coalesced over v. Wl fits in L2.
        acc += (coefBase * tw[k] * Wup[k]) * WlR[(size_t)k * 128];
    }

    // scatter into fragment-major layout (same mapping as rounds 8/9, verified)
    int ks = u >> 3, rem = u & 7;
    int tig = rem & 3, h = rem >> 2;
    int vt = v >> 3, gidv = v & 7;
    int lane = gidv * 4 + tig;
    int i2 = 2 * sec + h;
    int off;
    if (i2 < 12) off = (i2 >> 2) * 2048 + (ks * 32 + lane) * 4 + (i2 & 3);
    else         off = 6144 + (ks * 32 + lane) * 2 + (i2 - 12);
    g_Bf[vt * 7168 + off] = __uint_as_float(f2tf32(acc));
}

// ---------------- fused gemm + combine (round-6 structure, correct offsets) ----------------
// 64 nodes/block, 256 threads = 8 warps = 2 groups x 4 m-tiles of 16 rows.
#define ALD 516

// smem float offsets  (two-group layout — OFF_MF must follow BOTH O buffers)
#define OFF_A   0                     // 64*516  = 33024
#define OFF_B   33024                 // 2*7168  = 14336
#define OFF_O   47360                 // 2*4608  =  9216  (ends at 56576)
#define OFF_MF  56576                 //            576
#define SMEM_FLOATS 57152             // *4 = 228608 bytes

__device__ __forceinline__ void cp16(uint32_t dst, const void* src) {
    asm volatile("cp.async.cg.shared.global [%0], [%1], 16;" :: "r"(dst), "l"(src));
}
__device__ __forceinline__ void cp_commit() {
    asm volatile("cp.async.commit_group;");
}
__device__ __forceinline__ void group_bar(int id) {
    asm volatile("bar.sync %0, 128;" :: "r"(id) : "memory");
}

__device__ __forceinline__ void mma_tf32(float* d, const uint32_t* a, const uint32_t* b) {
    asm volatile(
        "mma.sync.aligned.m16n8k8.row.col.f32.tf32.tf32.f32 "
        "{%0,%1,%2,%3}, {%4,%5,%6,%7}, {%8,%9}, {%0,%1,%2,%3};"
        : "+f"(d[0]), "+f"(d[1]), "+f"(d[2]), "+f"(d[3])
        : "r"(a[0]), "r"(a[1]), "r"(a[2]), "r"(a[3]), "r"(b[0]), "r"(b[1]));
}

__global__ void __launch_bounds__(256, 1) fused_kernel(
        const float* __restrict__ nf, const float* __restrict__ mf,
        float* __restrict__ out) {
    extern __shared__ float sm[];
    uint32_t sbase = (uint32_t)__cvta_generic_to_shared(sm);

    int t = threadIdx.x;                 // 0..255
    int wid = t >> 5, lane = t & 31;
    int grp = wid >> 2;                  // 0/1
    int wg  = wid & 3;                   // m-tile within group
    int gt  = t & 127;                   // thread-in-group
    int gid = lane >> 2, tig = lane & 3;
    size_t nodeBase = (size_t)blockIdx.x * 64;

    // ---- initial staging: A raw + mf + group's first B tile ----
    {
        const float* srcA = nf + nodeBase * 512;
#pragma unroll
        for (int i = 0; i < 32; i++) {
            int idx = i * 256 + t;
            int node = idx >> 7, f4 = idx & 127;
            cp16(sbase + (OFF_A + node * ALD + f4 * 4) * 4,
                 srcA + (size_t)node * 512 + f4 * 4);
        }
        if (t < 144) cp16(sbase + (OFF_MF + t * 4) * 4, mf + nodeBase * 9 + t * 4);
        const float* srcB = g_Bf + (size_t)grp * 7168;   // first pass p0 = grp
#pragma unroll
        for (int i = 0; i < 14; i++) {
            int idx = i * 128 + gt;
            cp16(sbase + (OFF_B + grp * 7168 + idx * 4) * 4, srcB + idx * 4);
        }
        cp_commit();
    }
    asm volatile("cp.async.wait_group 0;");
    __syncthreads();

    // ---- in-place tf32 conversion of A (once) ----
#pragma unroll
    for (int i = 0; i < 33; i++) {
        int idx = i * 256 + t;
        if (idx < 8256) {
            float4 v4 = *reinterpret_cast<float4*>(sm + idx * 4);
            uint4 o = make_uint4(f2tf32(v4.x), f2tf32(v4.y), f2tf32(v4.z), f2tf32(v4.w));
            *reinterpret_cast<uint4*>(sm + idx * 4) = o;
        }
    }
    __syncthreads();

    const float r2 = 0.7071067811865476f;
    const float r6 = 0.4082482904638631f;
    const float i5 = 0.4472135954999579f;

    int rb = wg * 16;
    int r0row = (rb + gid) * ALD;
    int r1row = (rb + gid + 8) * ALD;
    const float* sB = sm + OFF_B + grp * 7168;
    float* sO = sm + OFF_O + grp * 4608;
    int barId = grp + 1;

    for (int i = 0; i < 8; i++) {
        int p = 2 * i + grp;

        asm volatile("cp.async.wait_group 0;");
        group_bar(barId);                      // B[p] visible to whole group

        float acc[15][4];
#pragma unroll
        for (int n = 0; n < 15; n++)
#pragma unroll
            for (int q = 0; q < 4; q++) acc[n][q] = 0.f;

#pragma unroll
        for (int ks = 0; ks < 16; ks++) {
            int kt = ks * 8 + tig;
            uint32_t ar[4][4];
            ar[0][0] = __float_as_uint(sm[r0row + kt]);
            ar[0][1] = __float_as_uint(sm[r1row + kt]);
            ar[0][2] = __float_as_uint(sm[r0row + kt + 4]);
            ar[0][3] = __float_as_uint(sm[r1row + kt + 4]);
#pragma unroll
            for (int a = 0; a < 3; a++) {
                int c0 = 128 + 3 * kt + a;
                ar[a + 1][0] = __float_as_uint(sm[r0row + c0]);
                ar[a + 1][1] = __float_as_uint(sm[r1row + c0]);
                ar[a + 1][2] = __float_as_uint(sm[r0row + c0 + 12]);
                ar[a + 1][3] = __float_as_uint(sm[r1row + c0 + 12]);
            }
            int slot = ks * 32 + lane;
            float4 b01 = *reinterpret_cast<const float4*>(sB + slot * 4);
            float4 b23 = *reinterpret_cast<const float4*>(sB + 2048 + slot * 4);
            float4 b45 = *reinterpret_cast<const float4*>(sB + 4096 + slot * 4);
            float2 b6  = *reinterpret_cast<const float2*>(sB + 6144 + slot * 2);
            uint32_t bf[7][2] = {
                {__float_as_uint(b01.x), __float_as_uint(b01.y)},
                {__float_as_uint(b01.z), __float_as_uint(b01.w)},
                {__float_as_uint(b23.x), __float_as_uint(b23.y)},
                {__float_as_uint(b23.z), __float_as_uint(b23.w)},
                {__float_as_uint(b45.x), __float_as_uint(b45.y)},
                {__float_as_uint(b45.z), __float_as_uint(b45.w)},
                {__float_as_uint(b6.x),  __float_as_uint(b6.y)}};
#pragma unroll
            for (int j = 0; j < 3; j++) mma_tf32(acc[j], ar[0], bf[j]);
#pragma unroll
            for (int a = 0; a < 3; a++)
#pragma unroll
                for (int j = 0; j < 4; j++) mma_tf32(acc[3 + a * 4 + j], ar[a + 1], bf[3 + j]);
        }

        group_bar(barId);                      // group done reading B[p]
        if (i < 7) {                           // prefetch B[p+2] (overlaps combine/store)
            const float* srcB = g_Bf + (size_t)(p + 2) * 7168;
#pragma unroll
            for (int q = 0; q < 14; q++) {
                int idx = q * 128 + gt;
                cp16(sbase + (OFF_B + grp * 7168 + idx * 4) * 4, srcB + idx * 4);
            }
            cp_commit();
        }

        // ---- combine -> smem staging ----
#pragma unroll
        for (int r = 0; r < 2; r++) {
            int nl = rb + gid + r * 8;
            const float* f = sm + OFF_MF + nl * 9;
            float f0  = f[0];
            float f1a = f[1], f1b = f[2], f1c = f[3];
            float f2a = f[4], f2b = f[5], f2c = f[6], f2d = f[7], f2e = f[8];

            float A00 = -f2c * r6 - f2e * r2;
            float A11 = 2.f * f2c * r6;
            float A22 = -f2c * r6 + f2e * r2;
            float A01 = f2b * r2, A02 = f2a * r2, A12 = f2d * r2;

#pragma unroll
            for (int c = 0; c < 2; c++) {
                int ai = r * 2 + c;
                int vl = tig * 2 + c;
                float y0 = acc[0][ai], y1 = acc[1][ai], y2 = acc[2][ai];
                float z00 = acc[3][ai],  z01 = acc[4][ai],  z02 = acc[5][ai],  z03 = acc[6][ai];
                float z10 = acc[7][ai],  z11 = acc[8][ai],  z12 = acc[9][ai],  z13 = acc[10][ai];
                float z20 = acc[11][ai], z21 = acc[12][ai], z22 = acc[13][ai], z23 = acc[14][ai];

                float* o = sO + nl * 72 + vl * 9;
                o[0] = f0 * y0 + f1a * z00 + f1b * z10 + f1c * z20;
                o[1] = f1a * y1 + f0 * z01 + i5 * (A00 * z02 + A01 * z12 + A02 * z22);
                o[2] = f1b * y1 + f0 * z11 + i5 * (A01 * z02 + A11 * z12 + A12 * z22);
                o[3] = f1c * y1 + f0 * z21 + i5 * (A02 * z02 + A12 * z12 + A22 * z22);
                o[4] = f2a * y2 + i5 * (f1c * r2 * z03 + f1a * r2 * z23);
                o[5] = f2b * y2 + i5 * (f1b * r2 * z03 + f1a * r2 * z13);
                o[6] = f2c * y2 + i5 * ((-f1a * z03 + 2.f * f1b * z13 - f1c * z23) * r6);
                o[7] = f2d * y2 + i5 * (f1c * r2 * z13 + f1b * r2 * z23);
                o[8] = f2e * y2 + i5 * ((-f1a * z03 + f1c * z23) * r2);
            }
        }
        group_bar(barId);                      // out tile staged

        // coalesced store: 64 nodes x 72 floats -> out[n*1152 + p*72 ..)
#pragma unroll
        for (int q = 0; q < 9; q++) {
            int idx = q * 128 + gt;            // 1152 float4s
            int node = idx / 18, f4i = idx - node * 18;
            float4 v4 = *reinterpret_cast<const float4*>(sO + node * 72 + f4i * 4);
            *reinterpret_cast<float4*>(out + (nodeBase + node) * 1152 + p * 72 + f4i * 4) = v4;
        }
        group_bar(barId);                      // out buffer free for next pass
    }
}

// ---------------- launch ----------------
extern "C" void kernel_launch(void* const* d_in, const int* in_sizes, int n_in,
                              void* d_out, int out_size) {
    const float* nf   = (const float*)d_in[0];
    const float* mf   = (const float*)d_in[1];
    const float* Wup0 = (const float*)d_in[2];
    const float* Wup1 = (const float*)d_in[3];
    const float* tpw  = (const float*)d_in[4];
    const float* Wl0  = (const float*)d_in[5];
    const float* Wl1  = (const float*)d_in[6];
    const float* Wl2  = (const float*)d_in[7];
    float* out = (float*)d_out;

    static bool attrSet = false;
    if (!attrSet) {
        cudaFuncSetAttribute(fused_kernel, cudaFuncAttributeMaxDynamicSharedMemorySize,
                             SMEM_FLOATS * 4);
        attrSet = true;
    }

    prep_kernel<<<896, 128>>>(Wup0, Wup1, tpw, Wl0, Wl1, Wl2);
    fused_kernel<<<NN / 64, 256, SMEM_FLOATS * 4>>>(nf, mf, out);
}

// round 13
// speedup vs baseline: 1.6828x; 1.0046x over previous
#include <cuda_runtime.h>
#include <cstdint>

#define NN 65536

// ---------------- globals ----------------
__device__ float g_Bf[16 * 7168];             // fragment-major folded B per v-tile

__device__ __forceinline__ uint32_t f2tf32(float f) {
    uint32_t u;
    asm("cvt.rna.tf32.f32 %0, %1;" : "=r"(u) : "f"(f));
    return u;
}

// ---------------- prep: fold weights, scatter into fragment-major g_Bf ----------------
// grid: 7 sections x 128 u-rows = 896 blocks, 128 threads (v). One u-row per block.
__global__ void __launch_bounds__(128) prep_kernel(
        const float* __restrict__ Wup0, const float* __restrict__ Wup1,
        const float* __restrict__ tpw,  const float* __restrict__ Wl0,
        const float* __restrict__ Wl1,  const float* __restrict__ Wl2) {
    const float INV_UP = 0.0883883476483184f;   // 1/sqrt(128)
    const float A2 = 0.7071067811865476f;       // 1/sqrt(2)
    const float A3 = 0.5773502691896258f;       // 1/sqrt(3)
    const float N0 = 0.0625f;                   // 1/sqrt(256)
    const float N1 = 0.0510310363079829f;       // 1/sqrt(384)
    const float R3 = 0.5773502691896258f;       // CG 1/sqrt(3)
    const float R5 = 0.4472135954999579f;       // CG 1/sqrt(5)

    int sec = blockIdx.x >> 7;     // 0..6
    int u   = blockIdx.x & 127;    // up-channel (GEMM K index)
    int v   = threadIdx.x;         // 0..127

    float coefBase; const float* Wl; int rowOff; int tpwIdx;
    switch (sec) {
        case 0: coefBase = A2 * N0;      Wl = Wl0; rowOff = 0;   tpwIdx = 0; break;
        case 1: coefBase = A3 * N1 * R3; Wl = Wl1; rowOff = 0;   tpwIdx = 1; break;
        case 2: coefBase = A2 * N0 * R5; Wl = Wl2; rowOff = 0;   tpwIdx = 2; break;
        case 3: coefBase = A2 * N0 * R3; Wl = Wl0; rowOff = 128; tpwIdx = 4; break;
        case 4: coefBase = A3 * N1 * R3; Wl = Wl1; rowOff = 128; tpwIdx = 3; break;
        case 5: coefBase = A3 * N1;      Wl = Wl1; rowOff = 256; tpwIdx = 6; break;
        default:coefBase = A2 * N0;      Wl = Wl2; rowOff = 128; tpwIdx = 5; break;
    }
    coefBase *= INV_UP;
    const float* Wup = ((sec < 3) ? Wup0 : Wup1) + (size_t)u * 128;
    const float* tw  = tpw + tpwIdx * 128;
    const float* WlR = Wl + (size_t)rowOff * 128 + v;

    float acc = 0.f;
#pragma unroll 16
    for (int k = 0; k < 128; k++) {
        // Wup[k], tw[k] warp-uniform; WlR coalesced over v. Wl fits in L2.
        acc += (coefBase * tw[k] * Wup[k]) * WlR[(size_t)k * 128];
    }

    // scatter into fragment-major layout (same mapping as rounds 8/9, verified)
    int ks = u >> 3, rem = u & 7;
    int tig = rem & 3, h = rem >> 2;
    int vt = v >> 3, gidv = v & 7;
    int lane = gidv * 4 + tig;
    int i2 = 2 * sec + h;
    int off;
    if (i2 < 12) off = (i2 >> 2) * 2048 + (ks * 32 + lane) * 4 + (i2 & 3);
    else         off = 6144 + (ks * 32 + lane) * 2 + (i2 - 12);
    g_Bf[vt * 7168 + off] = __uint_as_float(f2tf32(acc));
}

// ---------------- fused gemm + combine (round-6 structure, correct offsets) ----------------
// 64 nodes/block, 256 threads = 8 warps = 2 groups x 4 m-tiles of 16 rows.
#define ALD 516

// smem float offsets  (two-group layout — OFF_MF must follow BOTH O buffers)
#define OFF_A   0                     // 64*516  = 33024
#define OFF_B   33024                 // 2*7168  = 14336
#define OFF_O   47360                 // 2*4608  =  9216  (ends at 56576)
#define OFF_MF  56576                 //            576
#define SMEM_FLOATS 57152             // *4 = 228608 bytes

__device__ __forceinline__ void cp16(uint32_t dst, const void* src) {
    asm volatile("cp.async.cg.shared.global [%0], [%1], 16;" :: "r"(dst), "l"(src));
}
__device__ __forceinline__ void cp_commit() {
    asm volatile("cp.async.commit_group;");
}
__device__ __forceinline__ void group_bar(int id) {
    asm volatile("bar.sync %0, 128;" :: "r"(id) : "memory");
}

__device__ __forceinline__ void mma_tf32(float* d, const uint32_t* a, const uint32_t* b) {
    asm volatile(
        "mma.sync.aligned.m16n8k8.row.col.f32.tf32.tf32.f32 "
        "{%0,%1,%2,%3}, {%4,%5,%6,%7}, {%8,%9}, {%0,%1,%2,%3};"
        : "+f"(d[0]), "+f"(d[1]), "+f"(d[2]), "+f"(d[3])
        : "r"(a[0]), "r"(a[1]), "r"(a[2]), "r"(a[3]), "r"(b[0]), "r"(b[1]));
}

__global__ void __launch_bounds__(256, 1) fused_kernel(
        const float* __restrict__ nf, const float* __restrict__ mf,
        float* __restrict__ out) {
    extern __shared__ float sm[];
    uint32_t sbase = (uint32_t)__cvta_generic_to_shared(sm);

    int t = threadIdx.x;                 // 0..255
    int wid = t >> 5, lane = t & 31;
    int grp = wid >> 2;                  // 0/1
    int wg  = wid & 3;                   // m-tile within group
    int gt  = t & 127;                   // thread-in-group
    int gid = lane >> 2, tig = lane & 3;
    size_t nodeBase = (size_t)blockIdx.x * 64;

    // ---- initial staging: A raw + mf + group's first B tile ----
    {
        const float* srcA = nf + nodeBase * 512;
#pragma unroll
        for (int i = 0; i < 32; i++) {
            int idx = i * 256 + t;
            int node = idx >> 7, f4 = idx & 127;
            cp16(sbase + (OFF_A + node * ALD + f4 * 4) * 4,
                 srcA + (size_t)node * 512 + f4 * 4);
        }
        if (t < 144) cp16(sbase + (OFF_MF + t * 4) * 4, mf + nodeBase * 9 + t * 4);
        const float* srcB = g_Bf + (size_t)grp * 7168;   // first pass p0 = grp
#pragma unroll
        for (int i = 0; i < 14; i++) {
            int idx = i * 128 + gt;
            cp16(sbase + (OFF_B + grp * 7168 + idx * 4) * 4, srcB + idx * 4);
        }
        cp_commit();
    }
    asm volatile("cp.async.wait_group 0;");
    __syncthreads();

    // ---- in-place tf32 conversion of A (once) ----
#pragma unroll
    for (int i = 0; i < 33; i++) {
        int idx = i * 256 + t;
        if (idx < 8256) {
            float4 v4 = *reinterpret_cast<float4*>(sm + idx * 4);
            uint4 o = make_uint4(f2tf32(v4.x), f2tf32(v4.y), f2tf32(v4.z), f2tf32(v4.w));
            *reinterpret_cast<uint4*>(sm + idx * 4) = o;
        }
    }
    __syncthreads();

    const float r2 = 0.7071067811865476f;
    const float r6 = 0.4082482904638631f;
    const float i5 = 0.4472135954999579f;

    int rb = wg * 16;
    int r0row = (rb + gid) * ALD;
    int r1row = (rb + gid + 8) * ALD;
    const float* sB = sm + OFF_B + grp * 7168;
    float* sO = sm + OFF_O + grp * 4608;
    int barId = grp + 1;

    for (int i = 0; i < 8; i++) {
        int p = 2 * i + grp;

        asm volatile("cp.async.wait_group 0;");
        group_bar(barId);                      // B[p] visible to whole group

        float acc[15][4];
#pragma unroll
        for (int n = 0; n < 15; n++)
#pragma unroll
            for (int q = 0; q < 4; q++) acc[n][q] = 0.f;

#pragma unroll
        for (int ks = 0; ks < 16; ks++) {
            int kt = ks * 8 + tig;
            uint32_t ar[4][4];
            ar[0][0] = __float_as_uint(sm[r0row + kt]);
            ar[0][1] = __float_as_uint(sm[r1row + kt]);
            ar[0][2] = __float_as_uint(sm[r0row + kt + 4]);
            ar[0][3] = __float_as_uint(sm[r1row + kt + 4]);
#pragma unroll
            for (int a = 0; a < 3; a++) {
                int c0 = 128 + 3 * kt + a;
                ar[a + 1][0] = __float_as_uint(sm[r0row + c0]);
                ar[a + 1][1] = __float_as_uint(sm[r1row + c0]);
                ar[a + 1][2] = __float_as_uint(sm[r0row + c0 + 12]);
                ar[a + 1][3] = __float_as_uint(sm[r1row + c0 + 12]);
            }
            int slot = ks * 32 + lane;
            float4 b01 = *reinterpret_cast<const float4*>(sB + slot * 4);
            float4 b23 = *reinterpret_cast<const float4*>(sB + 2048 + slot * 4);
            float4 b45 = *reinterpret_cast<const float4*>(sB + 4096 + slot * 4);
            float2 b6  = *reinterpret_cast<const float2*>(sB + 6144 + slot * 2);
            uint32_t bf[7][2] = {
                {__float_as_uint(b01.x), __float_as_uint(b01.y)},
                {__float_as_uint(b01.z), __float_as_uint(b01.w)},
                {__float_as_uint(b23.x), __float_as_uint(b23.y)},
                {__float_as_uint(b23.z), __float_as_uint(b23.w)},
                {__float_as_uint(b45.x), __float_as_uint(b45.y)},
                {__float_as_uint(b45.z), __float_as_uint(b45.w)},
                {__float_as_uint(b6.x),  __float_as_uint(b6.y)}};
#pragma unroll
            for (int j = 0; j < 3; j++) mma_tf32(acc[j], ar[0], bf[j]);
#pragma unroll
            for (int a = 0; a < 3; a++)
#pragma unroll
                for (int j = 0; j < 4; j++) mma_tf32(acc[3 + a * 4 + j], ar[a + 1], bf[3 + j]);
        }

        group_bar(barId);                      // group done reading B[p]
        if (i < 7) {                           // prefetch B[p+2] (overlaps combine/store)
            const float* srcB = g_Bf + (size_t)(p + 2) * 7168;
#pragma unroll
            for (int q = 0; q < 14; q++) {
                int idx = q * 128 + gt;
                cp16(sbase + (OFF_B + grp * 7168 + idx * 4) * 4, srcB + idx * 4);
            }
            cp_commit();
        }

        // ---- combine -> smem staging ----
#pragma unroll
        for (int r = 0; r < 2; r++) {
            int nl = rb + gid + r * 8;
            const float* f = sm + OFF_MF + nl * 9;
            float f0  = f[0];
            float f1a = f[1], f1b = f[2], f1c = f[3];
            float f2a = f[4], f2b = f[5], f2c = f[6], f2d = f[7], f2e = f[8];

            float A00 = -f2c * r6 - f2e * r2;
            float A11 = 2.f * f2c * r6;
            float A22 = -f2c * r6 + f2e * r2;
            float A01 = f2b * r2, A02 = f2a * r2, A12 = f2d * r2;

#pragma unroll
            for (int c = 0; c < 2; c++) {
                int ai = r * 2 + c;
                int vl = tig * 2 + c;
                float y0 = acc[0][ai], y1 = acc[1][ai], y2 = acc[2][ai];
                float z00 = acc[3][ai],  z01 = acc[4][ai],  z02 = acc[5][ai],  z03 = acc[6][ai];
                float z10 = acc[7][ai],  z11 = acc[8][ai],  z12 = acc[9][ai],  z13 = acc[10][ai];
                float z20 = acc[11][ai], z21 = acc[12][ai], z22 = acc[13][ai], z23 = acc[14][ai];

                float* o = sO + nl * 72 + vl * 9;
                o[0] = f0 * y0 + f1a * z00 + f1b * z10 + f1c * z20;
                o[1] = f1a * y1 + f0 * z01 + i5 * (A00 * z02 + A01 * z12 + A02 * z22);
                o[2] = f1b * y1 + f0 * z11 + i5 * (A01 * z02 + A11 * z12 + A12 * z22);
                o[3] = f1c * y1 + f0 * z21 + i5 * (A02 * z02 + A12 * z12 + A22 * z22);
                o[4] = f2a * y2 + i5 * (f1c * r2 * z03 + f1a * r2 * z23);
                o[5] = f2b * y2 + i5 * (f1b * r2 * z03 + f1a * r2 * z13);
                o[6] = f2c * y2 + i5 * ((-f1a * z03 + 2.f * f1b * z13 - f1c * z23) * r6);
                o[7] = f2d * y2 + i5 * (f1c * r2 * z13 + f1b * r2 * z23);
                o[8] = f2e * y2 + i5 * ((-f1a * z03 + f1c * z23) * r2);
            }
        }
        group_bar(barId);                      // out tile staged

        // coalesced store: 64 nodes x 72 floats -> out[n*1152 + p*72 ..)
#pragma unroll
        for (int q = 0; q < 9; q++) {
            int idx = q * 128 + gt;            // 1152 float4s
            int node = idx / 18, f4i = idx - node * 18;
            float4 v4 = *reinterpret_cast<const float4*>(sO + node * 72 + f4i * 4);
            *reinterpret_cast<float4*>(out + (nodeBase + node) * 1152 + p * 72 + f4i * 4) = v4;
        }
        group_bar(barId);                      // out buffer free for next pass
    }
}

// ---------------- launch ----------------
extern "C" void kernel_launch(void* const* d_in, const int* in_sizes, int n_in,
                              void* d_out, int out_size) {
    const float* nf   = (const float*)d_in[0];
    const float* mf   = (const float*)d_in[1];
    const float* Wup0 = (const float*)d_in[2];
    const float* Wup1 = (const float*)d_in[3];
    const float* tpw  = (const float*)d_in[4];
    const float* Wl0  = (const float*)d_in[5];
    const float* Wl1  = (const float*)d_in[6];
    const float* Wl2  = (const float*)d_in[7];
    float* out = (float*)d_out;

    static bool attrSet = false;
    if (!attrSet) {
        cudaFuncSetAttribute(fused_kernel, cudaFuncAttributeMaxDynamicSharedMemorySize,
                             SMEM_FLOATS * 4);
        attrSet = true;
    }

    prep_kernel<<<896, 128>>>(Wup0, Wup1, tpw, Wl0, Wl1, Wl2);
    fused_kernel<<<NN / 64, 256, SMEM_FLOATS * 4>>>(nf, mf, out);
}